// round 1
// baseline (speedup 1.0000x reference)
#include <cuda_runtime.h>
#include <math.h>

// Shapes (fixed by the problem)
#define T_STEPS 32
#define NB      64
#define CDIM    512
#define ADIM    32
#define F1DIM   2048
#define F2DIM   1024
#define F3DIM   512

// ---------------- scratch (device globals; no allocation allowed) -------------
__device__ float g_F1[T_STEPS * NB * CDIM];    //  4 MB  filtered input to W1
__device__ float g_H1[T_STEPS * NB * F1DIM];   // 16 MB  W1 @ F1
__device__ float g_F2[T_STEPS * NB * F1DIM];   // 16 MB  filtered spikes layer1
__device__ float g_H2[T_STEPS * NB * F2DIM];   //  8 MB
__device__ float g_F3[T_STEPS * NB * F2DIM];   //  8 MB
__device__ float g_H3[T_STEPS * NB * F3DIM];   //  4 MB

__device__ __forceinline__ float sigmoid_acc(float w) {
    return 1.0f / (1.0f + expf(-w));
}

// ---------------------------------------------------------------------------
// Stage 1: transpose + Jeffress filter (tau=2) + w_jeff + LIF(tau=1.5)
//          + SynapseFilter(w_sf0) + w_cc reduction + IF + SynapseFilter(w_sf1)
// One warp per (n,c); lane = a (ADIM == 32 == warp size).
// ---------------------------------------------------------------------------
__global__ void stage1_kernel(const float* __restrict__ x,
                              const float* __restrict__ w_jeff,
                              const float* __restrict__ w_cc,
                              const float* __restrict__ w_sf0,
                              const float* __restrict__ w_sf1)
{
    int gw   = (blockIdx.x * blockDim.x + threadIdx.x) >> 5;
    int lane = threadIdx.x & 31;
    if (gw >= NB * CDIM) return;
    int n = gw / CDIM;
    int c = gw - n * CDIM;

    float wj0 = w_jeff[lane * 2 + 0];
    float wj1 = w_jeff[lane * 2 + 1];
    float wcc = w_cc[lane];
    float d0  = 1.0f - sigmoid_acc(w_sf0[0]);   // SynapseFilter after LIF
    float d1  = 1.0f - sigmoid_acc(w_sf1[0]);   // filter feeding W1
    const float invlif = 1.0f / 1.5f;

    float yf0 = 0.f, yf1 = 0.f;   // Jeffress low-pass states (decay 0.5)
    float v   = 0.f;              // LIF membrane (per a)
    float g   = 0.f;              // synapse trace (per a)
    float vI  = 0.f;              // IF membrane (per (n,c))
    float fo  = 0.f;              // filtered output trace

    const float* xb = x + (size_t)n * 2 * CDIM + c;
#pragma unroll
    for (int t = 0; t < T_STEPS; t++) {
        float x0 = xb[(size_t)t * NB * 2 * CDIM];
        float x1 = xb[(size_t)t * NB * 2 * CDIM + CDIM];
        yf0 = 0.5f * yf0 + x0;
        yf1 = 0.5f * yf1 + x1;
        float u = wj0 * yf0 + wj1 * yf1;
        v = v + (u - v) * invlif;
        float s = (v >= 1.0f) ? 1.0f : 0.0f;
        v = (v >= 1.0f) ? 0.0f : v;
        g = d0 * g + s;
        float r = g * wcc;
#pragma unroll
        for (int off = 16; off; off >>= 1)
            r += __shfl_xor_sync(0xffffffffu, r, off);
        // all lanes hold the a-sum now; replicate IF state across lanes
        vI += r;
        float s1 = (vI >= 1.0f) ? 1.0f : 0.0f;
        vI = (vI >= 1.0f) ? 0.0f : vI;
        fo = d1 * fo + s1;
        if (lane == 0)
            g_F1[((size_t)t * NB + n) * CDIM + c] = fo;
    }
}

// ---------------------------------------------------------------------------
// FP32 SIMT GEMM (NT): C[m][o] = sum_k A[o][k] * B[m][k]
// A: weights [Mo][K] row-major, B: activations [2048][K], C: [2048][Mo].
// 128x128 tile, BK=16, 256 threads, 8x8 microtile. All dims divide evenly.
// ---------------------------------------------------------------------------
__global__ void __launch_bounds__(256, 2)
gemm_nt_kernel(const float* __restrict__ A, const float* __restrict__ B,
               float* __restrict__ C, int Mo, int K)
{
    __shared__ float As[16][132];
    __shared__ float Bs[16][132];

    int bo  = blockIdx.x * 128;
    int bn  = blockIdx.y * 128;
    int tid = threadIdx.x;
    int tx  = tid & 15;
    int ty  = tid >> 4;

    float acc[8][8];
#pragma unroll
    for (int i = 0; i < 8; i++)
#pragma unroll
        for (int j = 0; j < 8; j++) acc[i][j] = 0.f;

    for (int k0 = 0; k0 < K; k0 += 16) {
#pragma unroll
        for (int l = 0; l < 2; l++) {
            int idx = tid + l * 256;
            int row = idx >> 2;
            int c4  = (idx & 3) * 4;
            float4 va = *reinterpret_cast<const float4*>(A + (size_t)(bo + row) * K + k0 + c4);
            As[c4 + 0][row] = va.x; As[c4 + 1][row] = va.y;
            As[c4 + 2][row] = va.z; As[c4 + 3][row] = va.w;
            float4 vb = *reinterpret_cast<const float4*>(B + (size_t)(bn + row) * K + k0 + c4);
            Bs[c4 + 0][row] = vb.x; Bs[c4 + 1][row] = vb.y;
            Bs[c4 + 2][row] = vb.z; Bs[c4 + 3][row] = vb.w;
        }
        __syncthreads();
#pragma unroll
        for (int kk = 0; kk < 16; kk++) {
            float a[8], b[8];
#pragma unroll
            for (int i = 0; i < 8; i++) a[i] = As[kk][ty * 8 + i];
#pragma unroll
            for (int j = 0; j < 8; j++) b[j] = Bs[kk][tx * 8 + j];
#pragma unroll
            for (int i = 0; i < 8; i++)
#pragma unroll
                for (int j = 0; j < 8; j++)
                    acc[i][j] = fmaf(a[i], b[j], acc[i][j]);
        }
        __syncthreads();
    }
#pragma unroll
    for (int j = 0; j < 8; j++) {
        float* cp = C + (size_t)(bn + tx * 8 + j) * Mo + bo + ty * 8;
        *reinterpret_cast<float4*>(cp + 0) =
            make_float4(acc[0][j], acc[1][j], acc[2][j], acc[3][j]);
        *reinterpret_cast<float4*>(cp + 4) =
            make_float4(acc[4][j], acc[5][j], acc[6][j], acc[7][j]);
    }
}

// ---------------------------------------------------------------------------
// IFNode over time + SynapseFilter(next block) fused.
// Thread per (n,o); reads H[t][n][o], writes filtered trace F[t][n][o].
// ---------------------------------------------------------------------------
__global__ void ifsyn_kernel(const float* __restrict__ H, float* __restrict__ F,
                             const float* __restrict__ w_sf, int Odim)
{
    int idx = blockIdx.x * blockDim.x + threadIdx.x;
    if (idx >= NB * Odim) return;
    int o = idx % Odim;
    int n = idx / Odim;
    float d = 1.0f - sigmoid_acc(w_sf[0]);
    float v = 0.f, f = 0.f;
#pragma unroll
    for (int t = 0; t < T_STEPS; t++) {
        size_t id = ((size_t)t * NB + n) * Odim + o;
        v += H[id];
        float s = (v >= 1.0f) ? 1.0f : 0.0f;
        v = (v >= 1.0f) ? 0.0f : v;
        f = d * f + s;
        F[id] = f;
    }
}

// ---------------------------------------------------------------------------
// Final: IF over H3, dot with W_out, + b_out, cumsum over t.
// One block per n, 512 threads = F3DIM.
// ---------------------------------------------------------------------------
__global__ void final_kernel(const float* __restrict__ Wout,
                             const float* __restrict__ bout,
                             float* __restrict__ out)
{
    int n = blockIdx.x;
    int f = threadIdx.x;
    __shared__ float red[16];
    float v   = 0.f;
    float wf  = Wout[f];
    float acc = 0.f;
    float b   = bout[0];
    int lane = f & 31, wid = f >> 5;
    for (int t = 0; t < T_STEPS; t++) {
        v += g_H3[((size_t)t * NB + n) * F3DIM + f];
        float s = (v >= 1.0f) ? 1.0f : 0.0f;
        v = (v >= 1.0f) ? 0.0f : v;
        float p = wf * s;
#pragma unroll
        for (int off = 16; off; off >>= 1)
            p += __shfl_xor_sync(0xffffffffu, p, off);
        if (lane == 0) red[wid] = p;
        __syncthreads();
        if (f < 16) {
            float q = red[f];
#pragma unroll
            for (int off = 8; off; off >>= 1)
                q += __shfl_xor_sync(0x0000ffffu, q, off);
            if (f == 0) {
                acc += q + b;
                out[t * NB + n] = acc;
            }
        }
        __syncthreads();
    }
}

// ---------------------------------------------------------------------------
extern "C" void kernel_launch(void* const* d_in, const int* in_sizes, int n_in,
                              void* d_out, int out_size)
{
    (void)in_sizes; (void)n_in; (void)out_size;
    const float* x     = (const float*)d_in[0];
    const float* wjeff = (const float*)d_in[1];
    const float* wcc   = (const float*)d_in[2];
    const float* wsf0  = (const float*)d_in[3];
    const float* W1    = (const float*)d_in[4];
    const float* wsf1  = (const float*)d_in[5];
    const float* W2    = (const float*)d_in[6];
    const float* wsf2  = (const float*)d_in[7];
    const float* W3    = (const float*)d_in[8];
    const float* wsf3  = (const float*)d_in[9];
    const float* Wout  = (const float*)d_in[10];
    const float* bout  = (const float*)d_in[11];
    float* out = (float*)d_out;

    float *F1, *H1, *F2, *H2, *F3, *H3;
    cudaGetSymbolAddress((void**)&F1, g_F1);
    cudaGetSymbolAddress((void**)&H1, g_H1);
    cudaGetSymbolAddress((void**)&F2, g_F2);
    cudaGetSymbolAddress((void**)&H2, g_H2);
    cudaGetSymbolAddress((void**)&F3, g_F3);
    cudaGetSymbolAddress((void**)&H3, g_H3);

    // Stage 1: one warp per (n,c): 32768 warps
    stage1_kernel<<<(NB * CDIM * 32) / 256, 256>>>(x, wjeff, wcc, wsf0, wsf1);

    // Block 1: W1 @ F1 -> H1 ; IF + filter(w_sf2) -> F2
    gemm_nt_kernel<<<dim3(F1DIM / 128, (T_STEPS * NB) / 128), 256>>>(W1, F1, H1, F1DIM, CDIM);
    ifsyn_kernel<<<(NB * F1DIM + 255) / 256, 256>>>(H1, F2, wsf2, F1DIM);

    // Block 2
    gemm_nt_kernel<<<dim3(F2DIM / 128, (T_STEPS * NB) / 128), 256>>>(W2, F2, H2, F2DIM, F1DIM);
    ifsyn_kernel<<<(NB * F2DIM + 255) / 256, 256>>>(H2, F3, wsf3, F2DIM);

    // Block 3
    gemm_nt_kernel<<<dim3(F3DIM / 128, (T_STEPS * NB) / 128), 256>>>(W3, F3, H3, F3DIM, F2DIM);

    // Final linear + NonSpikingIF cumsum
    final_kernel<<<NB, F3DIM>>>(Wout, bout, out);
}

// round 7
// speedup vs baseline: 1.0086x; 1.0086x over previous
#include <cuda_runtime.h>
#include <math.h>
#include <stdint.h>

// Shapes (fixed by the problem)
#define T_STEPS 32
#define NB      64
#define CDIM    512
#define F1DIM   2048
#define F2DIM   1024
#define F3DIM   512

typedef unsigned long long ull;

// ---------------- scratch (device globals; no allocation allowed) -------------
__device__ float g_F1[T_STEPS * NB * CDIM];    //  4 MB  filtered input to W1
__device__ float g_H1[T_STEPS * NB * F1DIM];   // 16 MB  W1 @ F1
__device__ float g_F2[T_STEPS * NB * F1DIM];   // 16 MB  filtered spikes layer1
__device__ float g_H2[T_STEPS * NB * F2DIM];   //  8 MB
__device__ float g_F3[T_STEPS * NB * F2DIM];   //  8 MB
__device__ float g_H3[T_STEPS * NB * F3DIM];   //  4 MB

__device__ __forceinline__ float sigmoid_acc(float w) {
    return 1.0f / (1.0f + expf(-w));
}

// ---------------------------------------------------------------------------
// Stage 1 (verbatim from passing R1)
// ---------------------------------------------------------------------------
__global__ void stage1_kernel(const float* __restrict__ x,
                              const float* __restrict__ w_jeff,
                              const float* __restrict__ w_cc,
                              const float* __restrict__ w_sf0,
                              const float* __restrict__ w_sf1)
{
    int gw   = (blockIdx.x * blockDim.x + threadIdx.x) >> 5;
    int lane = threadIdx.x & 31;
    if (gw >= NB * CDIM) return;
    int n = gw / CDIM;
    int c = gw - n * CDIM;

    float wj0 = w_jeff[lane * 2 + 0];
    float wj1 = w_jeff[lane * 2 + 1];
    float wcc = w_cc[lane];
    float d0  = 1.0f - sigmoid_acc(w_sf0[0]);
    float d1  = 1.0f - sigmoid_acc(w_sf1[0]);
    const float invlif = 1.0f / 1.5f;

    float yf0 = 0.f, yf1 = 0.f;
    float v   = 0.f;
    float g   = 0.f;
    float vI  = 0.f;
    float fo  = 0.f;

    const float* xb = x + (size_t)n * 2 * CDIM + c;
#pragma unroll
    for (int t = 0; t < T_STEPS; t++) {
        float x0 = xb[(size_t)t * NB * 2 * CDIM];
        float x1 = xb[(size_t)t * NB * 2 * CDIM + CDIM];
        yf0 = 0.5f * yf0 + x0;
        yf1 = 0.5f * yf1 + x1;
        float u = wj0 * yf0 + wj1 * yf1;
        v = v + (u - v) * invlif;
        float s = (v >= 1.0f) ? 1.0f : 0.0f;
        v = (v >= 1.0f) ? 0.0f : v;
        g = d0 * g + s;
        float r = g * wcc;
#pragma unroll
        for (int off = 16; off; off >>= 1)
            r += __shfl_xor_sync(0xffffffffu, r, off);
        vI += r;
        float s1 = (vI >= 1.0f) ? 1.0f : 0.0f;
        vI = (vI >= 1.0f) ? 0.0f : vI;
        fo = d1 * fo + s1;
        if (lane == 0)
            g_F1[((size_t)t * NB + n) * CDIM + c] = fo;
    }
}

// ---------------------------------------------------------------------------
// FP32 GEMM (NT) with packed f32x2 FMA. Bit-identical per-output chains to R1:
// acc[m][o] = fma(weight, activation, acc), k strictly ascending, one chain.
// C[m][o] = sum_k A[o][k] * B[m][k];  A weights [Mo][K], B acts [2048][K].
// 128x128 tile, BK=16, 256 threads, 8x8 microtile (o packed in pairs).
// ---------------------------------------------------------------------------
#define PADF 132    // floats per SMEM row (16B-aligned, conflict-free)

#define FMA2(acc, a, b) \
    asm("fma.rn.f32x2 %0, %1, %2, %0;" : "+l"(acc) : "l"(a), "l"(b))
#define PACK_DUP(d, s) \
    asm("mov.b64 %0, {%1, %1};" : "=l"(d) : "f"(s))
#define UNPACK2(lo, hi, v) \
    asm("mov.b64 {%0, %1}, %2;" : "=f"(lo), "=f"(hi) : "l"(v))

__global__ void __launch_bounds__(256, 2)
gemm_x2_kernel(const float* __restrict__ A, const float* __restrict__ B,
               float* __restrict__ C, int Mo, int K)
{
    __shared__ float As[2][16 * PADF];   // [k][o]
    __shared__ float Bs[2][16 * PADF];   // [k][m]

    int tid = threadIdx.x;
    int tx  = tid & 15;     // m-dir microtile
    int ty  = tid >> 4;     // o-dir microtile
    int bo  = blockIdx.x * 128;
    int bn  = blockIdx.y * 128;
    int NC  = K / 16;

    // loader role: first 128 threads load A (weights), rest load B (acts)
    int lr = tid & 127;
    const float* gsrc = (tid < 128)
        ? A + (size_t)(bo + lr) * K
        : B + (size_t)(bn + lr) * K;

    ull acc[4][8];
#pragma unroll
    for (int i = 0; i < 4; i++)
#pragma unroll
        for (int j = 0; j < 8; j++) acc[i][j] = 0ULL;

    float4 v0, v1, v2, v3;

    // prologue: load chunk 0
    v0 = *(const float4*)(gsrc + 0);
    v1 = *(const float4*)(gsrc + 4);
    v2 = *(const float4*)(gsrc + 8);
    v3 = *(const float4*)(gsrc + 12);

    for (int c = 0; c < NC; c++) {
        int buf = c & 1;
        // store chunk c (transpose to [k][row])
        {
            float* col = (tid < 128) ? &As[buf][lr] : &Bs[buf][lr];
            col[0 * PADF]  = v0.x; col[1 * PADF]  = v0.y;
            col[2 * PADF]  = v0.z; col[3 * PADF]  = v0.w;
            col[4 * PADF]  = v1.x; col[5 * PADF]  = v1.y;
            col[6 * PADF]  = v1.z; col[7 * PADF]  = v1.w;
            col[8 * PADF]  = v2.x; col[9 * PADF]  = v2.y;
            col[10 * PADF] = v2.z; col[11 * PADF] = v2.w;
            col[12 * PADF] = v3.x; col[13 * PADF] = v3.y;
            col[14 * PADF] = v3.z; col[15 * PADF] = v3.w;
        }
        __syncthreads();

        // prefetch chunk c+1 into regs
        if (c + 1 < NC) {
            const float* p = gsrc + (c + 1) * 16;
            v0 = *(const float4*)(p + 0);
            v1 = *(const float4*)(p + 4);
            v2 = *(const float4*)(p + 8);
            v3 = *(const float4*)(p + 12);
        }

        // compute on chunk c
#pragma unroll
        for (int k = 0; k < 16; k++) {
            const float* as = &As[buf][k * PADF + ty * 8];
            const float* bs = &Bs[buf][k * PADF + tx * 8];
            ulonglong2 t0 = *(const ulonglong2*)as;        // (a0,a1),(a2,a3)
            ulonglong2 t1 = *(const ulonglong2*)(as + 4);  // (a4,a5),(a6,a7)
            float4 b0 = *(const float4*)bs;
            float4 b1 = *(const float4*)(bs + 4);
            ull aP[4] = {t0.x, t0.y, t1.x, t1.y};
            ull bb[8];
            PACK_DUP(bb[0], b0.x); PACK_DUP(bb[1], b0.y);
            PACK_DUP(bb[2], b0.z); PACK_DUP(bb[3], b0.w);
            PACK_DUP(bb[4], b1.x); PACK_DUP(bb[5], b1.y);
            PACK_DUP(bb[6], b1.z); PACK_DUP(bb[7], b1.w);
#pragma unroll
            for (int j = 0; j < 8; j++)
#pragma unroll
                for (int i = 0; i < 4; i++)
                    FMA2(acc[i][j], aP[i], bb[j]);
        }
        __syncthreads();
    }

    // epilogue: row m = bn + tx*8 + j, cols o = bo + ty*8 .. +7
#pragma unroll
    for (int j = 0; j < 8; j++) {
        float r0, r1, r2, r3, r4, r5, r6, r7;
        UNPACK2(r0, r1, acc[0][j]);
        UNPACK2(r2, r3, acc[1][j]);
        UNPACK2(r4, r5, acc[2][j]);
        UNPACK2(r6, r7, acc[3][j]);
        float* cp = C + (size_t)(bn + tx * 8 + j) * Mo + bo + ty * 8;
        *reinterpret_cast<float4*>(cp + 0) = make_float4(r0, r1, r2, r3);
        *reinterpret_cast<float4*>(cp + 4) = make_float4(r4, r5, r6, r7);
    }
}

// ---------------------------------------------------------------------------
// IFNode over time + SynapseFilter(next block) fused (verbatim from R1).
// ---------------------------------------------------------------------------
__global__ void ifsyn_kernel(const float* __restrict__ H, float* __restrict__ F,
                             const float* __restrict__ w_sf, int Odim)
{
    int idx = blockIdx.x * blockDim.x + threadIdx.x;
    if (idx >= NB * Odim) return;
    int o = idx % Odim;
    int n = idx / Odim;
    float d = 1.0f - sigmoid_acc(w_sf[0]);
    float v = 0.f, f = 0.f;
#pragma unroll
    for (int t = 0; t < T_STEPS; t++) {
        size_t id = ((size_t)t * NB + n) * Odim + o;
        v += H[id];
        float s = (v >= 1.0f) ? 1.0f : 0.0f;
        v = (v >= 1.0f) ? 0.0f : v;
        f = d * f + s;
        F[id] = f;
    }
}

// ---------------------------------------------------------------------------
// Final: IF over H3, dot with W_out, + b_out, cumsum over t (verbatim R1).
// ---------------------------------------------------------------------------
__global__ void final_kernel(const float* __restrict__ Wout,
                             const float* __restrict__ bout,
                             float* __restrict__ out)
{
    int n = blockIdx.x;
    int f = threadIdx.x;
    __shared__ float red[16];
    float v   = 0.f;
    float wf  = Wout[f];
    float acc = 0.f;
    float b   = bout[0];
    int lane = f & 31, wid = f >> 5;
    for (int t = 0; t < T_STEPS; t++) {
        v += g_H3[((size_t)t * NB + n) * F3DIM + f];
        float s = (v >= 1.0f) ? 1.0f : 0.0f;
        v = (v >= 1.0f) ? 0.0f : v;
        float p = wf * s;
#pragma unroll
        for (int off = 16; off; off >>= 1)
            p += __shfl_xor_sync(0xffffffffu, p, off);
        if (lane == 0) red[wid] = p;
        __syncthreads();
        if (f < 16) {
            float q = red[f];
#pragma unroll
            for (int off = 8; off; off >>= 1)
                q += __shfl_xor_sync(0x0000ffffu, q, off);
            if (f == 0) {
                acc += q + b;
                out[t * NB + n] = acc;
            }
        }
        __syncthreads();
    }
}

// ---------------------------------------------------------------------------
extern "C" void kernel_launch(void* const* d_in, const int* in_sizes, int n_in,
                              void* d_out, int out_size)
{
    (void)in_sizes; (void)n_in; (void)out_size;
    const float* x     = (const float*)d_in[0];
    const float* wjeff = (const float*)d_in[1];
    const float* wcc   = (const float*)d_in[2];
    const float* wsf0  = (const float*)d_in[3];
    const float* W1    = (const float*)d_in[4];
    const float* wsf1  = (const float*)d_in[5];
    const float* W2    = (const float*)d_in[6];
    const float* wsf2  = (const float*)d_in[7];
    const float* W3    = (const float*)d_in[8];
    const float* wsf3  = (const float*)d_in[9];
    const float* Wout  = (const float*)d_in[10];
    const float* bout  = (const float*)d_in[11];
    float* out = (float*)d_out;

    float *F1, *H1, *F2, *H2, *F3, *H3;
    cudaGetSymbolAddress((void**)&F1, g_F1);
    cudaGetSymbolAddress((void**)&H1, g_H1);
    cudaGetSymbolAddress((void**)&F2, g_F2);
    cudaGetSymbolAddress((void**)&H2, g_H2);
    cudaGetSymbolAddress((void**)&F3, g_F3);
    cudaGetSymbolAddress((void**)&H3, g_H3);

    // Stage 1: one warp per (n,c)
    stage1_kernel<<<(NB * CDIM * 32) / 256, 256>>>(x, wjeff, wcc, wsf0, wsf1);

    // Block 1: W1 @ F1 -> H1 ; IF + filter(w_sf2) -> F2
    gemm_x2_kernel<<<dim3(F1DIM / 128, (T_STEPS * NB) / 128), 256>>>(W1, F1, H1, F1DIM, CDIM);
    ifsyn_kernel<<<(NB * F1DIM + 255) / 256, 256>>>(H1, F2, wsf2, F1DIM);

    // Block 2
    gemm_x2_kernel<<<dim3(F2DIM / 128, (T_STEPS * NB) / 128), 256>>>(W2, F2, H2, F2DIM, F1DIM);
    ifsyn_kernel<<<(NB * F2DIM + 255) / 256, 256>>>(H2, F3, wsf3, F2DIM);

    // Block 3
    gemm_x2_kernel<<<dim3(F3DIM / 128, (T_STEPS * NB) / 128), 256>>>(W3, F3, H3, F3DIM, F2DIM);

    // Final linear + NonSpikingIF cumsum
    final_kernel<<<NB, F3DIM>>>(Wout, bout, out);
}